// round 7
// baseline (speedup 1.0000x reference)
#include <cuda_runtime.h>
#include <cuda_bf16.h>
#include <cstdint>

#define NN 16384
#define DD 128
#define TOPK 32
#define NT 128
#define POOL 48

__device__ __nv_bfloat16 g_bh[(size_t)NN * DD];
__device__ int g_cand[(size_t)NN * 96];

__device__ __forceinline__ uint32_t smem_u32(const void* p) {
    uint32_t a;
    asm("{ .reg .u64 t; cvta.to.shared.u64 t, %1; cvt.u32.u64 %0, t; }" : "=r"(a) : "l"(p));
    return a;
}
#define CP16(dst, src) \
    asm volatile("cp.async.ca.shared.global [%0], [%1], 16;" :: "r"(dst), "l"(src))
#define CP_COMMIT() asm volatile("cp.async.commit_group;")
#define CP_WAIT0() asm volatile("cp.async.wait_group 0;")
#define LDSM4(r0, r1, r2, r3, a) \
    asm volatile("ldmatrix.sync.aligned.m8n8.x4.shared.b16 {%0,%1,%2,%3}, [%4];" \
        : "=r"(r0), "=r"(r1), "=r"(r2), "=r"(r3) : "r"(a))
#define MMA16816(c, a0, a1, a2, a3, b0, b1) \
    asm volatile("mma.sync.aligned.m16n8k16.row.col.f32.bf16.bf16.f32 " \
        "{%0,%1,%2,%3}, {%4,%5,%6,%7}, {%8,%9}, {%0,%1,%2,%3};" \
        : "+f"((c)[0]), "+f"((c)[1]), "+f"((c)[2]), "+f"((c)[3]) \
        : "r"(a0), "r"(a1), "r"(a2), "r"(a3), "r"(b0), "r"(b1))
#define BAR_SYNC(id, n) asm volatile("bar.sync %0, %1;" :: "r"(id), "r"(n) : "memory")
#define BAR_ARRIVE(id, n) asm volatile("bar.arrive %0, %1;" :: "r"(id), "r"(n) : "memory")
// pack two f32 -> bf16x2 (lo = a, hi = b)
#define PACK_BF16X2(r, a, b) \
    asm("cvt.rn.bf16x2.f32 %0, %1, %2;" : "=r"(r) : "f"(b), "f"(a))

#define SM_A 0
#define SM_B 34816            // 2 x 34816
#define SM_C 104448           // 2 x 34816 (bf16, stride 136 elems = 272 B)
#define SM_PEND 174080        // 256 x 136
#define SMEM_TOTAL 208896

__global__ void split_kernel(const float* __restrict__ W) {
    int i = blockIdx.x * blockDim.x + threadIdx.x;
    if (i < NN * DD) g_bh[i] = __float2bfloat16(W[i]);
}

__device__ __forceinline__ void pool_insert(float* pv, int* pid, float& curmin,
                                            float v, int id) {
    bool d = false;
#pragma unroll
    for (int q = 0; q < POOL; q++) {
        bool mt = (!d) && (pv[q] == curmin);
        if (mt) { pv[q] = v; pid[q] = id; }
        d = d || mt;
    }
    float mn = pv[0];
#pragma unroll
    for (int q = 1; q < POOL; q++) mn = fminf(mn, pv[q]);
    curmin = mn;
}

__device__ __forceinline__ void flushbuf(float* pv, int* pid, float& curmin, int& cnt,
                                         uint2* pend) {
    int kmax = cnt;
#pragma unroll
    for (int o = 16; o; o >>= 1) kmax = max(kmax, __shfl_xor_sync(0xffffffffu, kmax, o));
#pragma unroll 1
    for (int j = 0; j < kmax; j++) {
        if (j < cnt) {
            uint2 e = pend[j];
            float v = __uint_as_float(e.x);
            if (v > curmin) pool_insert(pv, pid, curmin, v, (int)e.y);
        }
    }
    cnt = 0;
}

__global__ void __launch_bounds__(512, 1) fused_kernel() {
    extern __shared__ char smem[];
    const uint32_t sb = smem_u32(smem);
    const int tid = threadIdx.x;
    const int row0 = blockIdx.x * 128;

    if (tid < 256) {
        // ===================== producers: loads + MMA =====================
        const int wid = tid >> 5, lane = tid & 31;
        const int mbase = (wid & 3) * 32, nbase = (wid >> 2) * 64;
        const int srow = tid >> 1, shalf = tid & 1;

        {   // prologue: A tile + B(0)
            const char* asrc = (const char*)(g_bh + (size_t)(row0 + srow) * DD + shalf * 64);
            const char* bsrc = (const char*)(g_bh + (size_t)srow * DD + shalf * 64);
            uint32_t adst = sb + SM_A + srow * 272 + shalf * 128;
            uint32_t bdst = sb + SM_B + srow * 272 + shalf * 128;
#pragma unroll
            for (int q = 0; q < 8; q++) {
                CP16(adst + q * 16, asrc + q * 16);
                CP16(bdst + q * 16, bsrc + q * 16);
            }
            CP_COMMIT();
            CP_WAIT0();
            BAR_SYNC(1, 256);
        }

#pragma unroll 1
        for (int t = 0; t < NT; t++) {
            if (t + 1 < NT) {
                const char* bsrc =
                    (const char*)(g_bh + (size_t)((t + 1) * 128 + srow) * DD + shalf * 64);
                uint32_t bdst = sb + SM_B + ((t + 1) & 1) * 34816 + srow * 272 + shalf * 128;
#pragma unroll
                for (int q = 0; q < 8; q++) CP16(bdst + q * 16, bsrc + q * 16);
                CP_COMMIT();
            }

            float c[2][8][4];
#pragma unroll
            for (int mi = 0; mi < 2; mi++)
#pragma unroll
                for (int ni = 0; ni < 8; ni++)
#pragma unroll
                    for (int q = 0; q < 4; q++) c[mi][ni][q] = 0.0f;

            const uint32_t Ab = sb + SM_A + (mbase + (lane & 15)) * 272 + (lane >> 4) * 16;
            const uint32_t Bb = sb + SM_B + (t & 1) * 34816 +
                                (nbase + (lane & 15)) * 272 + (lane >> 4) * 16;
#pragma unroll
            for (int ks = 0; ks < 8; ks++) {
                uint32_t a[2][4], b[8][2];
#pragma unroll
                for (int mi = 0; mi < 2; mi++)
                    LDSM4(a[mi][0], a[mi][1], a[mi][2], a[mi][3],
                          Ab + mi * 16 * 272 + ks * 32);
#pragma unroll
                for (int pi = 0; pi < 4; pi++) {
                    uint32_t r0, r1, r2, r3;
                    LDSM4(r0, r1, r2, r3, Bb + pi * 16 * 272 + ks * 32);
                    b[2 * pi][0] = r0; b[2 * pi][1] = r2;
                    b[2 * pi + 1][0] = r1; b[2 * pi + 1][1] = r3;
                }
#pragma unroll
                for (int mi = 0; mi < 2; mi++)
#pragma unroll
                    for (int ni = 0; ni < 8; ni++)
                        MMA16816(c[mi][ni], a[mi][0], a[mi][1], a[mi][2], a[mi][3],
                                 b[ni][0], b[ni][1]);
            }

            const int p = t & 1;
            if (t >= 2) BAR_SYNC(4 + p, 512);   // buffer p EMPTY
            char* Cb = smem + SM_C + p * 34816;
#pragma unroll
            for (int mi = 0; mi < 2; mi++)
#pragma unroll
                for (int ni = 0; ni < 8; ni++) {
                    int r = mbase + mi * 16 + (lane >> 2);
                    int col = nbase + ni * 8 + (lane & 3) * 2;
                    uint32_t p0, p1;
                    PACK_BF16X2(p0, c[mi][ni][0], c[mi][ni][1]);
                    PACK_BF16X2(p1, c[mi][ni][2], c[mi][ni][3]);
                    *(uint32_t*)(Cb + r * 272 + col * 2) = p0;
                    *(uint32_t*)(Cb + (r + 8) * 272 + col * 2) = p1;
                }
            BAR_ARRIVE(2 + p, 512);             // buffer p FULL

            CP_WAIT0();
            BAR_SYNC(1, 256);
        }
    } else {
        // ===================== scanners: per-row top-48 pool =====================
        const int s = tid - 256;
        const int srow = s >> 1, shalf = s & 1;

        float pv[POOL]; int pid[POOL];
#pragma unroll
        for (int q = 0; q < POOL; q++) { pv[q] = -3.4e38f; pid[q] = 0; }
        float curmin = -3.4e38f;
        int cnt = 0;
        uint2* pend = (uint2*)(smem + SM_PEND + s * 136);

#pragma unroll 1
        for (int t = 0; t < NT; t++) {
            const int p = t & 1;
            BAR_SYNC(2 + p, 512);               // wait FULL
            const char* Crow = smem + SM_C + p * 34816 + srow * 272 + shalf * 128;
            const int cbase = t * 128 + shalf * 64;
#pragma unroll 1
            for (int jb = 0; jb < 8; jb++) {
                uint4 u = *(const uint4*)(Crow + jb * 16);
                const uint32_t uu[4] = {u.x, u.y, u.z, u.w};
#pragma unroll
                for (int q = 0; q < 4; q++) {
                    float lo = __uint_as_float(uu[q] << 16);
                    float hi = __uint_as_float(uu[q] & 0xffff0000u);
                    int base = cbase + jb * 8 + q * 2;
                    if (lo > curmin) { pend[cnt] = make_uint2(__float_as_uint(lo), (uint32_t)base); cnt++; }
                    if (hi > curmin) { pend[cnt] = make_uint2(__float_as_uint(hi), (uint32_t)(base + 1)); cnt++; }
                }
                if (__any_sync(0xffffffffu, cnt >= 8)) flushbuf(pv, pid, curmin, cnt, pend);
            }
            BAR_ARRIVE(4 + p, 512);             // EMPTY
        }
        flushbuf(pv, pid, curmin, cnt, pend);

        int* cd = g_cand + (size_t)(row0 + srow) * 96 + shalf * POOL;
#pragma unroll
        for (int q = 0; q < POOL; q++) cd[q] = pid[q];
    }
}

// ---------------- exact refinement (unchanged) --------
__device__ __forceinline__ void sort32_desc(float& v, int& i, int lane) {
#pragma unroll
    for (int k = 2; k <= 32; k <<= 1)
#pragma unroll
        for (int j = k >> 1; j > 0; j >>= 1) {
            float ov = __shfl_xor_sync(0xffffffffu, v, j);
            int oi = __shfl_xor_sync(0xffffffffu, i, j);
            bool self_big = (v > ov) || (v == ov && i < oi);
            bool keep = (self_big == (!(lane & j) == !(lane & k)));
            if (!keep) { v = ov; i = oi; }
        }
}
__device__ __forceinline__ void merge32_desc(float& v, int& i, int lane) {
#pragma unroll
    for (int j = 16; j > 0; j >>= 1) {
        float ov = __shfl_xor_sync(0xffffffffu, v, j);
        int oi = __shfl_xor_sync(0xffffffffu, i, j);
        bool self_big = (v > ov) || (v == ov && i < oi);
        if (!(self_big == !(lane & j))) { v = ov; i = oi; }
    }
}
__device__ __forceinline__ void sort32_by_idx_asc(float& v, int& i, int lane) {
#pragma unroll
    for (int k = 2; k <= 32; k <<= 1)
#pragma unroll
        for (int j = k >> 1; j > 0; j >>= 1) {
            float ov = __shfl_xor_sync(0xffffffffu, v, j);
            int oi = __shfl_xor_sync(0xffffffffu, i, j);
            bool keep = ((i < oi) == (!(lane & j) == !(lane & k)));
            if (!keep) { v = ov; i = oi; }
        }
}

__global__ void __launch_bounds__(256) refine_kernel(const float* __restrict__ W,
                                                     float* __restrict__ out) {
    const int wid = threadIdx.x >> 5, lane = threadIdx.x & 31;
    const int row = blockIdx.x * 8 + wid;
    const float4 x4 = *(const float4*)(W + (size_t)row * DD + lane * 4);
    const int* cd = g_cand + (size_t)row * 96;

    float v[3]; int id[3];
#pragma unroll 1
    for (int b = 0; b < 3; b++) {
        int myc = cd[b * 32 + lane];
        float acc = 0.0f;
#pragma unroll 1
        for (int j = 0; j < 32; j++) {
            int cidx = __shfl_sync(0xffffffffu, myc, j);
            float4 w4 = *(const float4*)(W + (size_t)cidx * DD + lane * 4);
            float s = x4.x * w4.x + x4.y * w4.y + x4.z * w4.z + x4.w * w4.w;
#pragma unroll
            for (int o = 16; o; o >>= 1) s += __shfl_xor_sync(0xffffffffu, s, o);
            if (lane == j) acc = s;
        }
        v[b] = acc; id[b] = myc;
    }

    sort32_desc(v[0], id[0], lane);
#pragma unroll 1
    for (int b = 1; b < 3; b++) {
        sort32_desc(v[b], id[b], lane);
        float rv = __shfl_sync(0xffffffffu, v[b], 31 - lane);
        int ri = __shfl_sync(0xffffffffu, id[b], 31 - lane);
        if (rv > v[0] || (rv == v[0] && ri < id[0])) { v[0] = rv; id[0] = ri; }
        merge32_desc(v[0], id[0], lane);
    }
    sort32_by_idx_asc(v[0], id[0], lane);

    const size_t NK = (size_t)NN * TOPK;
    size_t o = (size_t)row * TOPK + lane;
    out[o] = (float)row;
    out[NK + o] = (float)id[0];
    out[2 * NK + o] = v[0];
}

extern "C" void kernel_launch(void* const* d_in, const int* in_sizes, int n_in,
                              void* d_out, int out_size) {
    const float* W = nullptr;
    for (int i = 0; i < n_in; i++)
        if (in_sizes[i] == NN * DD) W = (const float*)d_in[i];
    if (!W) W = (const float*)d_in[n_in - 1];

    cudaFuncSetAttribute(fused_kernel, cudaFuncAttributeMaxDynamicSharedMemorySize,
                         SMEM_TOTAL);
    split_kernel<<<(NN * DD + 255) / 256, 256>>>(W);
    fused_kernel<<<NN / 128, 512, SMEM_TOTAL>>>();
    refine_kernel<<<NN / 8, 256>>>(W, (float*)d_out);
}

// round 8
// speedup vs baseline: 1.4480x; 1.4480x over previous
#include <cuda_runtime.h>
#include <cuda_bf16.h>
#include <cstdint>

#define NN 16384
#define DD 128
#define TOPK 32
#define NT 128
#define POOL 48

__device__ __nv_bfloat16 g_bh[(size_t)NN * DD];
__device__ int g_cand[(size_t)NN * 96];
__device__ int g_sync;

__device__ __forceinline__ uint32_t smem_u32(const void* p) {
    uint32_t a;
    asm("{ .reg .u64 t; cvta.to.shared.u64 t, %1; cvt.u32.u64 %0, t; }" : "=r"(a) : "l"(p));
    return a;
}
#define CP16(dst, src) \
    asm volatile("cp.async.ca.shared.global [%0], [%1], 16;" :: "r"(dst), "l"(src))
#define CP_COMMIT() asm volatile("cp.async.commit_group;")
#define CP_WAIT0() asm volatile("cp.async.wait_group 0;")
#define LDSM4(r0, r1, r2, r3, a) \
    asm volatile("ldmatrix.sync.aligned.m8n8.x4.shared.b16 {%0,%1,%2,%3}, [%4];" \
        : "=r"(r0), "=r"(r1), "=r"(r2), "=r"(r3) : "r"(a))
#define MMA16816(c, a0, a1, a2, a3, b0, b1) \
    asm volatile("mma.sync.aligned.m16n8k16.row.col.f32.bf16.bf16.f32 " \
        "{%0,%1,%2,%3}, {%4,%5,%6,%7}, {%8,%9}, {%0,%1,%2,%3};" \
        : "+f"((c)[0]), "+f"((c)[1]), "+f"((c)[2]), "+f"((c)[3]) \
        : "r"(a0), "r"(a1), "r"(a2), "r"(a3), "r"(b0), "r"(b1))
#define BAR_SYNC(id, n) asm volatile("bar.sync %0, %1;" :: "r"(id), "r"(n) : "memory")
#define BAR_ARRIVE(id, n) asm volatile("bar.arrive %0, %1;" :: "r"(id), "r"(n) : "memory")

#define SM_A 0
#define SM_B 34816
#define SM_C 104448
#define SM_PEND 172032
#define SMEM_TOTAL 206848

__device__ __forceinline__ void pool_insert(float* pv, int* pid, float& curmin,
                                            float v, int id) {
    bool d = false;
#pragma unroll
    for (int q = 0; q < POOL; q++) {
        bool mt = (!d) && (pv[q] == curmin);
        if (mt) { pv[q] = v; pid[q] = id; }
        d = d || mt;
    }
    float mn = pv[0];
#pragma unroll
    for (int q = 1; q < POOL; q++) mn = fminf(mn, pv[q]);
    curmin = mn;
}

__device__ __forceinline__ void flushbuf(float* pv, int* pid, float& curmin, int& cnt,
                                         uint2* pend) {
    int kmax = cnt;
#pragma unroll
    for (int o = 16; o; o >>= 1) kmax = max(kmax, __shfl_xor_sync(0xffffffffu, kmax, o));
#pragma unroll 1
    for (int j = 0; j < kmax; j++) {
        if (j < cnt) {
            uint2 e = pend[j];
            float v = __uint_as_float(e.x);
            if (v > curmin) pool_insert(pv, pid, curmin, v, (int)e.y);
        }
    }
    cnt = 0;
}

__global__ void __launch_bounds__(512, 1) fused_kernel(const float* __restrict__ W) {
    extern __shared__ char smem[];
    const uint32_t sb = smem_u32(smem);
    const int tid = threadIdx.x;
    const int row0 = blockIdx.x * 128;
    float* C = (float*)(smem + SM_C);

    // ---- inline bf16 split of this CTA's 128-row strip ----
    {
        const float* src = W + (size_t)row0 * DD;
        __nv_bfloat16* dst = g_bh + (size_t)row0 * DD;
#pragma unroll
        for (int q = 0; q < 32; q++) {
            int i = tid + q * 512;
            dst[i] = __float2bfloat16(src[i]);
        }
        __threadfence();
        __syncthreads();
        if (tid == 0) {
            atomicAdd(&g_sync, 1);
            while (atomicAdd(&g_sync, 0) < NN / 128) { }
        }
        __syncthreads();
        __threadfence();
    }

    if (tid < 256) {
        // ===================== producers: loads + MMA =====================
        const int wid = tid >> 5, lane = tid & 31;
        const int mbase = (wid & 3) * 32, nbase = (wid >> 2) * 64;
        const int srow = tid >> 1, shalf = tid & 1;

        {   // prologue: A tile + B(0)
            const char* asrc = (const char*)(g_bh + (size_t)(row0 + srow) * DD + shalf * 64);
            const char* bsrc = (const char*)(g_bh + (size_t)srow * DD + shalf * 64);
            uint32_t adst = sb + SM_A + srow * 272 + shalf * 128;
            uint32_t bdst = sb + SM_B + srow * 272 + shalf * 128;
#pragma unroll
            for (int q = 0; q < 8; q++) {
                CP16(adst + q * 16, asrc + q * 16);
                CP16(bdst + q * 16, bsrc + q * 16);
            }
            CP_COMMIT();
            CP_WAIT0();
            BAR_SYNC(1, 256);
        }

#pragma unroll 1
        for (int t = 0; t < NT; t++) {
            if (t + 1 < NT) {
                const char* bsrc =
                    (const char*)(g_bh + (size_t)((t + 1) * 128 + srow) * DD + shalf * 64);
                uint32_t bdst = sb + SM_B + ((t + 1) & 1) * 34816 + srow * 272 + shalf * 128;
#pragma unroll
                for (int q = 0; q < 8; q++) CP16(bdst + q * 16, bsrc + q * 16);
                CP_COMMIT();
            }

            float c[2][8][4];
#pragma unroll
            for (int mi = 0; mi < 2; mi++)
#pragma unroll
                for (int ni = 0; ni < 8; ni++)
#pragma unroll
                    for (int q = 0; q < 4; q++) c[mi][ni][q] = 0.0f;

            const uint32_t Ab = sb + SM_A + (mbase + (lane & 15)) * 272 + (lane >> 4) * 16;
            const uint32_t Bb = sb + SM_B + (t & 1) * 34816 +
                                (nbase + (lane & 15)) * 272 + (lane >> 4) * 16;
#pragma unroll
            for (int ks = 0; ks < 8; ks++) {
                uint32_t a[2][4], b[8][2];
#pragma unroll
                for (int mi = 0; mi < 2; mi++)
                    LDSM4(a[mi][0], a[mi][1], a[mi][2], a[mi][3],
                          Ab + mi * 16 * 272 + ks * 32);
#pragma unroll
                for (int pi = 0; pi < 4; pi++) {
                    uint32_t r0, r1, r2, r3;
                    LDSM4(r0, r1, r2, r3, Bb + pi * 16 * 272 + ks * 32);
                    b[2 * pi][0] = r0; b[2 * pi][1] = r2;
                    b[2 * pi + 1][0] = r1; b[2 * pi + 1][1] = r3;
                }
#pragma unroll
                for (int mi = 0; mi < 2; mi++)
#pragma unroll
                    for (int ni = 0; ni < 8; ni++)
                        MMA16816(c[mi][ni], a[mi][0], a[mi][1], a[mi][2], a[mi][3],
                                 b[ni][0], b[ni][1]);
            }

            if (t) BAR_SYNC(3, 512);  // wait scanners done with C (EMPTY)
#pragma unroll
            for (int mi = 0; mi < 2; mi++)
#pragma unroll
                for (int ni = 0; ni < 8; ni++) {
                    int r = mbase + mi * 16 + (lane >> 2);
                    int col = nbase + ni * 8 + (lane & 3) * 2;
                    *(float2*)&C[r * 132 + col] = make_float2(c[mi][ni][0], c[mi][ni][1]);
                    *(float2*)&C[(r + 8) * 132 + col] = make_float2(c[mi][ni][2], c[mi][ni][3]);
                }
            BAR_ARRIVE(2, 512);  // FULL

            CP_WAIT0();
            BAR_SYNC(1, 256);
        }
    } else {
        // ===================== scanners: per-row top-48 pool =====================
        const int s = tid - 256;
        const int srow = s >> 1, shalf = s & 1;

        float pv[POOL]; int pid[POOL];
#pragma unroll
        for (int q = 0; q < POOL; q++) { pv[q] = -3.4e38f; pid[q] = 0; }
        float curmin = -3.4e38f;
        int cnt = 0;
        uint2* pend = (uint2*)(smem + SM_PEND + s * 136);

#pragma unroll 1
        for (int t = 0; t < NT; t++) {
            BAR_SYNC(2, 512);  // wait FULL
            const float* Crow = C + srow * 132 + shalf * 64;
            const int cbase = t * 128 + shalf * 64;
#pragma unroll 1
            for (int jb = 0; jb < 4; jb++) {
                float4 v0 = *(const float4*)(Crow + jb * 16);
                float4 v1 = *(const float4*)(Crow + jb * 16 + 4);
                float4 v2 = *(const float4*)(Crow + jb * 16 + 8);
                float4 v3 = *(const float4*)(Crow + jb * 16 + 12);
                const float vv[16] = {v0.x, v0.y, v0.z, v0.w, v1.x, v1.y, v1.z, v1.w,
                                      v2.x, v2.y, v2.z, v2.w, v3.x, v3.y, v3.z, v3.w};
#pragma unroll
                for (int j = 0; j < 16; j++) {
                    float v = vv[j];
                    if (v > curmin) {
                        pend[cnt] = make_uint2(__float_as_uint(v),
                                               (uint32_t)(cbase + jb * 16 + j));
                        cnt++;
                    }
                    if ((j & 7) == 7) {
                        if (__any_sync(0xffffffffu, cnt >= 8))
                            flushbuf(pv, pid, curmin, cnt, pend);
                    }
                }
            }
            BAR_ARRIVE(3, 512);  // EMPTY
        }
        flushbuf(pv, pid, curmin, cnt, pend);

        int* cd = g_cand + (size_t)(row0 + srow) * 96 + shalf * POOL;
#pragma unroll
        for (int q = 0; q < POOL; q++) cd[q] = pid[q];
    }
}

// ---------------- exact refinement (unchanged) --------
__device__ __forceinline__ void sort32_desc(float& v, int& i, int lane) {
#pragma unroll
    for (int k = 2; k <= 32; k <<= 1)
#pragma unroll
        for (int j = k >> 1; j > 0; j >>= 1) {
            float ov = __shfl_xor_sync(0xffffffffu, v, j);
            int oi = __shfl_xor_sync(0xffffffffu, i, j);
            bool self_big = (v > ov) || (v == ov && i < oi);
            bool keep = (self_big == (!(lane & j) == !(lane & k)));
            if (!keep) { v = ov; i = oi; }
        }
}
__device__ __forceinline__ void merge32_desc(float& v, int& i, int lane) {
#pragma unroll
    for (int j = 16; j > 0; j >>= 1) {
        float ov = __shfl_xor_sync(0xffffffffu, v, j);
        int oi = __shfl_xor_sync(0xffffffffu, i, j);
        bool self_big = (v > ov) || (v == ov && i < oi);
        if (!(self_big == !(lane & j))) { v = ov; i = oi; }
    }
}
__device__ __forceinline__ void sort32_by_idx_asc(float& v, int& i, int lane) {
#pragma unroll
    for (int k = 2; k <= 32; k <<= 1)
#pragma unroll
        for (int j = k >> 1; j > 0; j >>= 1) {
            float ov = __shfl_xor_sync(0xffffffffu, v, j);
            int oi = __shfl_xor_sync(0xffffffffu, i, j);
            bool keep = ((i < oi) == (!(lane & j) == !(lane & k)));
            if (!keep) { v = ov; i = oi; }
        }
}

__global__ void __launch_bounds__(256) refine_kernel(const float* __restrict__ W,
                                                     float* __restrict__ out) {
    const int wid = threadIdx.x >> 5, lane = threadIdx.x & 31;
    const int row = blockIdx.x * 8 + wid;
    const float4 x4 = *(const float4*)(W + (size_t)row * DD + lane * 4);
    const int* cd = g_cand + (size_t)row * 96;

    float v[3]; int id[3];
#pragma unroll 1
    for (int b = 0; b < 3; b++) {
        int myc = cd[b * 32 + lane];
        float acc = 0.0f;
#pragma unroll 1
        for (int j = 0; j < 32; j++) {
            int cidx = __shfl_sync(0xffffffffu, myc, j);
            float4 w4 = *(const float4*)(W + (size_t)cidx * DD + lane * 4);
            float s = x4.x * w4.x + x4.y * w4.y + x4.z * w4.z + x4.w * w4.w;
#pragma unroll
            for (int o = 16; o; o >>= 1) s += __shfl_xor_sync(0xffffffffu, s, o);
            if (lane == j) acc = s;
        }
        v[b] = acc; id[b] = myc;
    }

    sort32_desc(v[0], id[0], lane);
#pragma unroll 1
    for (int b = 1; b < 3; b++) {
        sort32_desc(v[b], id[b], lane);
        float rv = __shfl_sync(0xffffffffu, v[b], 31 - lane);
        int ri = __shfl_sync(0xffffffffu, id[b], 31 - lane);
        if (rv > v[0] || (rv == v[0] && ri < id[0])) { v[0] = rv; id[0] = ri; }
        merge32_desc(v[0], id[0], lane);
    }
    sort32_by_idx_asc(v[0], id[0], lane);

    const size_t NK = (size_t)NN * TOPK;
    size_t o = (size_t)row * TOPK + lane;
    out[o] = (float)row;
    out[NK + o] = (float)id[0];
    out[2 * NK + o] = v[0];
}

__global__ void reset_kernel() { g_sync = 0; }

extern "C" void kernel_launch(void* const* d_in, const int* in_sizes, int n_in,
                              void* d_out, int out_size) {
    const float* W = nullptr;
    for (int i = 0; i < n_in; i++)
        if (in_sizes[i] == NN * DD) W = (const float*)d_in[i];
    if (!W) W = (const float*)d_in[n_in - 1];

    cudaFuncSetAttribute(fused_kernel, cudaFuncAttributeMaxDynamicSharedMemorySize,
                         SMEM_TOTAL);
    fused_kernel<<<NN / 128, 512, SMEM_TOTAL>>>(W);
    refine_kernel<<<NN / 8, 256>>>(W, (float*)d_out);
    reset_kernel<<<1, 1>>>();
}